// round 14
// baseline (speedup 1.0000x reference)
#include <cuda_runtime.h>
#include <cuda_bf16.h>
#include <cstdint>

#define TB 1024
#define BB 4
#define ROWB 64u     // bytes per granule row: 32 bf16

// dynamic smem layout (bytes)
#define OFF_FH   0u
#define OFF_FL   16384u
#define OFF_KH   32768u
#define OFF_KL   49152u
#define OFF_WQH  65536u
#define OFF_WQL  67584u
#define OFF_WKH  69632u
#define OFF_WKL  71680u
#define DSMEM_BYTES 73728

// Granule layout: row r = 4 x uint4; slot s comp j = bf16 pair (s+4j) = cols {2(s+4j), 2(s+4j)+1}.

// ---------------- helpers ----------------
static __device__ __forceinline__ float ex2f(float v) {
    float y; asm("ex2.approx.ftz.f32 %0, %1;" : "=f"(y) : "f"(v)); return y;
}
static __device__ __forceinline__ void psplit(float e, float o, uint32_t& hi, uint32_t& lo) {
    __nv_bfloat16 he = __float2bfloat16(e), ho = __float2bfloat16(o);
    __nv_bfloat162 hp(he, ho);
    hi = *reinterpret_cast<uint32_t*>(&hp);
    __nv_bfloat162 lp(__float2bfloat16(e - __bfloat162float(he)),
                      __float2bfloat16(o - __bfloat162float(ho)));
    lo = *reinterpret_cast<uint32_t*>(&lp);
}
static __device__ __forceinline__ void mma16816(float* d, const uint32_t* a,
                                                uint32_t b0, uint32_t b1) {
    asm("mma.sync.aligned.m16n8k16.row.col.f32.bf16.bf16.f32 "
        "{%0,%1,%2,%3}, {%4,%5,%6,%7}, {%8,%9}, {%0,%1,%2,%3};"
        : "+f"(d[0]), "+f"(d[1]), "+f"(d[2]), "+f"(d[3])
        : "r"(a[0]), "r"(a[1]), "r"(a[2]), "r"(a[3]), "r"(b0), "r"(b1));
}

// ---------------- kernel ----------------
// One CTA per (b,t), 256 threads, 2 CTAs/SM. All GEMMs on HMMA.
// Phase 1: warp w stages ITS OWN channels 32w..32w+31 (2 ch x 16 lanes per pass),
//          psplit in flight, granules stored directly (no f32 staging buffer).
// Phase 2: merged q/k projection MMA; q outputs stay in registers as attention
//          A-fragments; k outputs -> smem granules. A-frags are warp-local.
// Phase 3: attention, max-free log2 softmax (logits >= 0, constant shift -32).
// Only 2 __syncthreads total.
__global__ void __launch_bounds__(256, 2)
csa_mma_kernel(const float* __restrict__ x,
               const float* __restrict__ kw,  const float* __restrict__ kbias,
               const float* __restrict__ kg,  const float* __restrict__ kbeta,
               const float* __restrict__ qw,  const float* __restrict__ qbias,
               const float* __restrict__ qg,  const float* __restrict__ qbeta,
               float* __restrict__ out)
{
    extern __shared__ char dsm[];
    __shared__ __align__(8) float s_v[256];
    __shared__ float s_bq[32], s_bk[32];

    char* FH = dsm + OFF_FH;  char* FL = dsm + OFF_FL;
    char* KH = dsm + OFF_KH;  char* KL = dsm + OFF_KL;

    const int t   = blockIdx.x;
    const int b   = blockIdx.y;
    const int tid = threadIdx.x;
    const int w   = tid >> 5;
    const int l   = tid & 31;
    const int g   = l >> 2;    // fragment row group
    const int cq  = l & 3;     // quad col id (granule slot)

    const float inv    = rsqrtf(1.0f + 1e-5f);
    const float qscale = 0.17677669529663687f * 1.4426950408889634f; // (1/sqrt32)*log2(e)

    // ---- 1a. weight granules (folded BN; qscale folded into q) + biases ----
    {
        const int m    = tid >> 7;          // 0 = q, 1 = k
        const int slot = tid & 127;
        const int s    = slot >> 2;
        const int i    = slot & 3;
        const float* wsrc = m ? kw : qw;
        const float* gsrc = m ? kg : qg;
        float gs = gsrc[s] * inv * (m ? 1.0f : qscale);
        uint32_t gh[4], gl[4];
        #pragma unroll
        for (int j = 0; j < 4; j++) {
            int d0 = 2 * (i + 4 * j);
            float2 wv = *(const float2*)(wsrc + s * 32 + d0);
            psplit(wv.x * gs, wv.y * gs, gh[j], gl[j]);
        }
        char* WH = dsm + (m ? OFF_WKH : OFF_WQH);
        char* WL = dsm + (m ? OFF_WKL : OFF_WQL);
        *(uint4*)(WH + s * 64 + i * 16) = make_uint4(gh[0], gh[1], gh[2], gh[3]);
        *(uint4*)(WL + s * 64 + i * 16) = make_uint4(gl[0], gl[1], gl[2], gl[3]);
        if (tid < 32)
            s_bq[tid] = (qbias[tid] * qg[tid] * inv + qbeta[tid]) * qscale;
        else if (tid < 64) {
            int ss = tid - 32;
            s_bk[ss] = kbias[ss] * kg[ss] * inv + kbeta[ss];
        }
    }

    // ---- 1b. stage own-warp channels directly into granules (split on load) ----
    {
        const int d2  = l & 15;            // pair index 0..15
        const int sub = l >> 4;            // 0/1: which of 2 channels this pass
        const int tau = t - 31 + 2 * d2;
        const uint32_t goff = (uint32_t)((d2 & 3) * 16 + (d2 >> 2) * 4);
        #pragma unroll
        for (int p = 0; p < 16; p++) {
            const int c = 32 * w + 2 * p + sub;
            const float* xr = x + ((size_t)(b * 256 + c)) * TB;
            float e = (tau >= 0)     ? xr[tau]     : 0.0f;
            float o = (tau + 1 >= 0) ? xr[tau + 1] : 0.0f;
            uint32_t hi, lo;
            psplit(e, o, hi, lo);
            uint32_t off = (uint32_t)c * ROWB + goff;
            *(uint32_t*)(FH + off) = hi;
            *(uint32_t*)(FL + off) = lo;
            if (d2 == 15) s_v[c] = o;
        }
    }
    __syncthreads();   // weights + all framed granules + s_v visible

    // ---- 2. merged projection MMA (A-frags are warp-local rows 32w..32w+31) ----
    uint32_t aqh[2][2][4], aql[2][2][4];   // attention A-frags (q outputs)
    {
        uint32_t ah[2][2][4], al[2][2][4];
        #pragma unroll
        for (int mt = 0; mt < 2; mt++) {
            uint32_t r0 = (uint32_t)(32 * w + 16 * mt + g) * ROWB + (uint32_t)cq * 16u;
            uint4 h0 = *(const uint4*)(FH + r0);
            uint4 h1 = *(const uint4*)(FH + r0 + 8 * ROWB);
            uint4 l0 = *(const uint4*)(FL + r0);
            uint4 l1 = *(const uint4*)(FL + r0 + 8 * ROWB);
            ah[mt][0][0] = h0.x; ah[mt][0][1] = h1.x; ah[mt][0][2] = h0.y; ah[mt][0][3] = h1.y;
            ah[mt][1][0] = h0.z; ah[mt][1][1] = h1.z; ah[mt][1][2] = h0.w; ah[mt][1][3] = h1.w;
            al[mt][0][0] = l0.x; al[mt][0][1] = l1.x; al[mt][0][2] = l0.y; al[mt][0][3] = l1.y;
            al[mt][1][0] = l0.z; al[mt][1][1] = l1.z; al[mt][1][2] = l0.w; al[mt][1][3] = l1.w;
        }

        uint32_t oh[4][4], ol[4][4];       // k outputs [row r][nt]
        #pragma unroll
        for (int nt = 0; nt < 4; nt++) {
            uint32_t woff = (uint32_t)(8 * nt + g) * ROWB + (uint32_t)cq * 16u;
            uint4 wqh = *(const uint4*)(dsm + OFF_WQH + woff);
            uint4 wql = *(const uint4*)(dsm + OFF_WQL + woff);
            uint4 wkh = *(const uint4*)(dsm + OFF_WKH + woff);
            uint4 wkl = *(const uint4*)(dsm + OFF_WKL + woff);
            float2 bq2 = *(const float2*)(s_bq + 8 * nt + 2 * cq);
            float2 bk2 = *(const float2*)(s_bk + 8 * nt + 2 * cq);
            #pragma unroll
            for (int mt = 0; mt < 2; mt++) {
                float a4[4] = {bq2.x, bq2.y, bq2.x, bq2.y};
                mma16816(a4, ah[mt][0], wqh.x, wqh.y);
                mma16816(a4, ah[mt][1], wqh.z, wqh.w);
                mma16816(a4, ah[mt][0], wql.x, wql.y);
                mma16816(a4, ah[mt][1], wql.z, wql.w);
                mma16816(a4, al[mt][0], wqh.x, wqh.y);
                mma16816(a4, al[mt][1], wqh.z, wqh.w);

                float c4[4] = {bk2.x, bk2.y, bk2.x, bk2.y};
                mma16816(c4, ah[mt][0], wkh.x, wkh.y);
                mma16816(c4, ah[mt][1], wkh.z, wkh.w);
                mma16816(c4, ah[mt][0], wkl.x, wkl.y);
                mma16816(c4, ah[mt][1], wkl.z, wkl.w);
                mma16816(c4, al[mt][0], wkh.x, wkh.y);
                mma16816(c4, al[mt][1], wkh.z, wkh.w);

                const int k2 = nt >> 1, hx = 2 * (nt & 1);
                psplit(fmaxf(a4[0], 0.0f), fmaxf(a4[1], 0.0f),
                       aqh[mt][k2][hx + 0], aql[mt][k2][hx + 0]);   // row g
                psplit(fmaxf(a4[2], 0.0f), fmaxf(a4[3], 0.0f),
                       aqh[mt][k2][hx + 1], aql[mt][k2][hx + 1]);   // row g+8
                psplit(fmaxf(c4[0], 0.0f), fmaxf(c4[1], 0.0f),
                       oh[mt * 2 + 0][nt], ol[mt * 2 + 0][nt]);
                psplit(fmaxf(c4[2], 0.0f), fmaxf(c4[3], 0.0f),
                       oh[mt * 2 + 1][nt], ol[mt * 2 + 1][nt]);
            }
        }
        #pragma unroll
        for (int r = 0; r < 4; r++) {
            int row = 32 * w + 16 * (r >> 1) + 8 * (r & 1) + g;
            uint32_t off = (uint32_t)row * ROWB + (uint32_t)cq * 16u;
            *(uint4*)(KH + off) = make_uint4(oh[r][0], oh[r][1], oh[r][2], oh[r][3]);
            *(uint4*)(KL + off) = make_uint4(ol[r][0], ol[r][1], ol[r][2], ol[r][3]);
        }
    }
    __syncthreads();   // all K granules visible

    // ---- 3. attention: max-free, acc initialized to -32 (exact shift) ----
    float stD[4], stN[4];
    #pragma unroll
    for (int r = 0; r < 4; r++) { stD[r] = 0.0f; stN[r] = 0.0f; }

    const char* KHg = KH + (uint32_t)g * ROWB + (uint32_t)cq * 16u;
    const char* KLg = KL + (uint32_t)g * ROWB + (uint32_t)cq * 16u;

    #pragma unroll 4
    for (int ch = 0; ch < 16; ch++) {
        uint4 bh[2], blo[2];
        #pragma unroll
        for (int nt = 0; nt < 2; nt++) {
            bh[nt]  = *(const uint4*)(KHg + ((uint32_t)ch * 16u + 8u * nt) * ROWB);
            blo[nt] = *(const uint4*)(KLg + ((uint32_t)ch * 16u + 8u * nt) * ROWB);
        }
        float2 v0 = *(const float2*)&s_v[16 * ch + 2 * cq];
        float2 v1 = *(const float2*)&s_v[16 * ch + 8 + 2 * cq];

        float acc[2][2][4];
        #pragma unroll
        for (int mt = 0; mt < 2; mt++)
            #pragma unroll
            for (int nt = 0; nt < 2; nt++) {
                float* a = acc[mt][nt];
                a[0] = a[1] = a[2] = a[3] = -32.0f;   // constant softmax shift
                mma16816(a, aqh[mt][0], bh[nt].x,  bh[nt].y);
                mma16816(a, aqh[mt][1], bh[nt].z,  bh[nt].w);
                mma16816(a, aqh[mt][0], blo[nt].x, blo[nt].y);
                mma16816(a, aqh[mt][1], blo[nt].z, blo[nt].w);
                mma16816(a, aql[mt][0], bh[nt].x,  bh[nt].y);
                mma16816(a, aql[mt][1], bh[nt].z,  bh[nt].w);
            }

        #pragma unroll
        for (int mt = 0; mt < 2; mt++)
            #pragma unroll
            for (int i = 0; i < 2; i++) {
                int r = mt * 2 + i;
                float e0 = ex2f(acc[mt][0][2 * i + 0]);
                float e1 = ex2f(acc[mt][0][2 * i + 1]);
                float e2 = ex2f(acc[mt][1][2 * i + 0]);
                float e3 = ex2f(acc[mt][1][2 * i + 1]);
                stD[r] += (e0 + e1) + (e2 + e3);
                stN[r] += (e0 * v0.x + e1 * v0.y) + (e2 * v1.x + e3 * v1.y);
            }
    }

    // ---- quad merge (pure adds) + write ----
    #pragma unroll
    for (int r = 0; r < 4; r++) {
        #pragma unroll
        for (int off = 1; off <= 2; off <<= 1) {
            stD[r] += __shfl_xor_sync(0xffffffffu, stD[r], off);
            stN[r] += __shfl_xor_sync(0xffffffffu, stN[r], off);
        }
    }
    if (cq == 0) {
        #pragma unroll
        for (int r = 0; r < 4; r++) {
            int row = 32 * w + (r >> 1) * 16 + (r & 1) * 8 + g;
            out[((size_t)(b * 256 + row)) * TB + t] = s_v[row] + stN[r] / stD[r];
        }
    }
}

extern "C" void kernel_launch(void* const* d_in, const int* in_sizes, int n_in,
                              void* d_out, int out_size) {
    const float* x    = (const float*)d_in[0];
    const float* kw   = (const float*)d_in[1];
    const float* kb   = (const float*)d_in[2];
    const float* kg   = (const float*)d_in[3];
    const float* kbe  = (const float*)d_in[4];
    const float* qw   = (const float*)d_in[5];
    const float* qb   = (const float*)d_in[6];
    const float* qg   = (const float*)d_in[7];
    const float* qbe  = (const float*)d_in[8];
    float* o = (float*)d_out;

    cudaFuncSetAttribute(csa_mma_kernel, cudaFuncAttributeMaxDynamicSharedMemorySize, DSMEM_BYTES);
    dim3 grid(TB, BB);
    csa_mma_kernel<<<grid, 256, DSMEM_BYTES>>>(x, kw, kb, kg, kbe, qw, qb, qg, qbe, o);
}

// round 15
// speedup vs baseline: 1.1227x; 1.1227x over previous
#include <cuda_runtime.h>
#include <cuda_bf16.h>
#include <cstdint>

#define TB 1024
#define BB 4
#define ROWB 64u     // bytes per granule row: 32 bf16
#define XROW 33      // f32 staging row stride (floats), conflict-free

// dynamic smem layout (bytes) — s_x NOT overlaid (removes one barrier)
#define OFF_SX   0u          // 256 * 33 * 4 = 33792
#define OFF_FH   33792u
#define OFF_FL   50176u
#define OFF_KH   66560u
#define OFF_KL   82944u
#define OFF_WQH  99328u
#define OFF_WQL  101376u
#define OFF_WKH  103424u
#define OFF_WKL  105472u
#define DSMEM_BYTES 107520

// Granule layout: row r = 4 x uint4; slot s comp j = bf16 pair (s+4j) = cols {2(s+4j), 2(s+4j)+1}.

// ---------------- helpers ----------------
static __device__ __forceinline__ uint32_t smem_u32(const void* p) {
    uint32_t a;
    asm("{ .reg .u64 t; cvta.to.shared.u64 t, %1; cvt.u32.u64 %0, t; }" : "=r"(a) : "l"(p));
    return a;
}
static __device__ __forceinline__ float ex2f(float v) {
    float y; asm("ex2.approx.ftz.f32 %0, %1;" : "=f"(y) : "f"(v)); return y;
}
static __device__ __forceinline__ void psplit(float e, float o, uint32_t& hi, uint32_t& lo) {
    __nv_bfloat16 he = __float2bfloat16(e), ho = __float2bfloat16(o);
    __nv_bfloat162 hp(he, ho);
    hi = *reinterpret_cast<uint32_t*>(&hp);
    __nv_bfloat162 lp(__float2bfloat16(e - __bfloat162float(he)),
                      __float2bfloat16(o - __bfloat162float(ho)));
    lo = *reinterpret_cast<uint32_t*>(&lp);
}
static __device__ __forceinline__ void mma16816(float* d, const uint32_t* a,
                                                uint32_t b0, uint32_t b1) {
    asm("mma.sync.aligned.m16n8k16.row.col.f32.bf16.bf16.f32 "
        "{%0,%1,%2,%3}, {%4,%5,%6,%7}, {%8,%9}, {%0,%1,%2,%3};"
        : "+f"(d[0]), "+f"(d[1]), "+f"(d[2]), "+f"(d[3])
        : "r"(a[0]), "r"(a[1]), "r"(a[2]), "r"(a[3]), "r"(b0), "r"(b1));
}

// ---------------- kernel ----------------
// One CTA per (b,t), 256 threads, 2 CTAs/SM. All GEMMs on HMMA.
// R11 base (bulk staging, separate q/k proj, max-free log2 softmax) plus:
//  - s_x un-overlaid -> one fewer __syncthreads
//  - final barrier replaced by per-producer-warp flags: warp w starts attention
//    on its OWN K rows immediately, rotates p=(w+j)&7, acquire-polls flag[p].
__global__ void __launch_bounds__(256, 2)
csa_mma_kernel(const float* __restrict__ x,
               const float* __restrict__ kw,  const float* __restrict__ kbias,
               const float* __restrict__ kg,  const float* __restrict__ kbeta,
               const float* __restrict__ qw,  const float* __restrict__ qbias,
               const float* __restrict__ qg,  const float* __restrict__ qbeta,
               float* __restrict__ out)
{
    extern __shared__ char dsm[];
    __shared__ __align__(8) float s_v[256];
    __shared__ float s_bq[32], s_bk[32];
    __shared__ int s_flag[8];

    float* s_x = (float*)(dsm + OFF_SX);
    char* FH = dsm + OFF_FH;  char* FL = dsm + OFF_FL;
    char* KH = dsm + OFF_KH;  char* KL = dsm + OFF_KL;

    const int t   = blockIdx.x;
    const int b   = blockIdx.y;
    const int tid = threadIdx.x;
    const int w   = tid >> 5;
    const int l   = tid & 31;
    const int g   = l >> 2;    // fragment row group
    const int cq  = l & 3;     // quad col id (granule slot)

    const float inv    = rsqrtf(1.0f + 1e-5f);
    const float qscale = 0.17677669529663687f * 1.4426950408889634f; // (1/sqrt32)*log2(e)

    if (tid < 8) s_flag[tid] = 0;

    // ---- 1a. stage windows coalesced: lane = time offset ----
    {
        const float* xb = x + ((size_t)b * 256) * TB;
        #pragma unroll
        for (int i = tid; i < 256 * 32; i += 256) {
            int c = i >> 5, d = i & 31;
            int tau = t - 31 + d;
            s_x[c * XROW + d] = (tau >= 0) ? xb[(size_t)c * TB + tau] : 0.0f;
        }
    }

    // ---- 1b. weight granules (folded BN; qscale folded into q) + biases ----
    {
        const int m    = tid >> 7;          // 0 = q, 1 = k
        const int slot = tid & 127;
        const int s    = slot >> 2;
        const int i    = slot & 3;
        const float* wsrc = m ? kw : qw;
        const float* gsrc = m ? kg : qg;
        float gs = gsrc[s] * inv * (m ? 1.0f : qscale);
        uint32_t gh[4], gl[4];
        #pragma unroll
        for (int j = 0; j < 4; j++) {
            int d0 = 2 * (i + 4 * j);
            float2 wv = *(const float2*)(wsrc + s * 32 + d0);
            psplit(wv.x * gs, wv.y * gs, gh[j], gl[j]);
        }
        char* WH = dsm + (m ? OFF_WKH : OFF_WQH);
        char* WL = dsm + (m ? OFF_WKL : OFF_WQL);
        *(uint4*)(WH + s * 64 + i * 16) = make_uint4(gh[0], gh[1], gh[2], gh[3]);
        *(uint4*)(WL + s * 64 + i * 16) = make_uint4(gl[0], gl[1], gl[2], gl[3]);
        if (tid < 32)
            s_bq[tid] = (qbias[tid] * qg[tid] * inv + qbeta[tid]) * qscale;
        else if (tid < 64) {
            int ss = tid - 32;
            s_bk[ss] = kbias[ss] * kg[ss] * inv + kbeta[ss];
        }
    }
    __syncthreads();   // staging + weights + flag init visible

    // ---- 2. split own framed row -> granule stores (no overlay, no extra sync) ----
    {
        const float* xr = s_x + tid * XROW;
        float f[32];
        #pragma unroll
        for (int d = 0; d < 32; d++) f[d] = xr[d];
        s_v[tid] = f[31];
        uint4* dh = (uint4*)(FH + tid * ROWB);
        uint4* dl = (uint4*)(FL + tid * ROWB);
        #pragma unroll
        for (int i = 0; i < 4; i++) {
            uint32_t h0, l0, h1, l1, h2, l2, h3, l3;
            psplit(f[2*i],      f[2*i+1],      h0, l0);
            psplit(f[2*(i+4)],  f[2*(i+4)+1],  h1, l1);
            psplit(f[2*(i+8)],  f[2*(i+8)+1],  h2, l2);
            psplit(f[2*(i+12)], f[2*(i+12)+1], h3, l3);
            dh[i] = make_uint4(h0, h1, h2, h3);
            dl[i] = make_uint4(l0, l1, l2, l3);
        }
    }
    __syncthreads();   // all framed granules + s_v visible

    // ---- 3. projection MMA ----
    uint32_t aqh[2][2][4], aql[2][2][4];   // attention A-frags (q outputs)
    {
        uint32_t ah[2][2][4], al[2][2][4];
        #pragma unroll
        for (int mt = 0; mt < 2; mt++) {
            uint32_t r0 = (uint32_t)(32 * w + 16 * mt + g) * ROWB + (uint32_t)cq * 16u;
            uint4 h0 = *(const uint4*)(FH + r0);
            uint4 h1 = *(const uint4*)(FH + r0 + 8 * ROWB);
            uint4 l0 = *(const uint4*)(FL + r0);
            uint4 l1 = *(const uint4*)(FL + r0 + 8 * ROWB);
            ah[mt][0][0] = h0.x; ah[mt][0][1] = h1.x; ah[mt][0][2] = h0.y; ah[mt][0][3] = h1.y;
            ah[mt][1][0] = h0.z; ah[mt][1][1] = h1.z; ah[mt][1][2] = h0.w; ah[mt][1][3] = h1.w;
            al[mt][0][0] = l0.x; al[mt][0][1] = l1.x; al[mt][0][2] = l0.y; al[mt][0][3] = l1.y;
            al[mt][1][0] = l0.z; al[mt][1][1] = l1.z; al[mt][1][2] = l0.w; al[mt][1][3] = l1.w;
        }

        // k first: outputs -> smem granules, then release flag
        {
            uint32_t oh[4][4], ol[4][4];
            #pragma unroll
            for (int nt = 0; nt < 4; nt++) {
                uint32_t woff = (uint32_t)(8 * nt + g) * ROWB + (uint32_t)cq * 16u;
                uint4 wh = *(const uint4*)(dsm + OFF_WKH + woff);
                uint4 wl = *(const uint4*)(dsm + OFF_WKL + woff);
                float2 bb = *(const float2*)(s_bk + 8 * nt + 2 * cq);
                #pragma unroll
                for (int mt = 0; mt < 2; mt++) {
                    float a4[4] = {bb.x, bb.y, bb.x, bb.y};
                    mma16816(a4, ah[mt][0], wh.x, wh.y);
                    mma16816(a4, ah[mt][1], wh.z, wh.w);
                    mma16816(a4, ah[mt][0], wl.x, wl.y);
                    mma16816(a4, ah[mt][1], wl.z, wl.w);
                    mma16816(a4, al[mt][0], wh.x, wh.y);
                    mma16816(a4, al[mt][1], wh.z, wh.w);
                    #pragma unroll
                    for (int i = 0; i < 2; i++)
                        psplit(fmaxf(a4[2 * i + 0], 0.0f), fmaxf(a4[2 * i + 1], 0.0f),
                               oh[mt * 2 + i][nt], ol[mt * 2 + i][nt]);
                }
            }
            #pragma unroll
            for (int r = 0; r < 4; r++) {
                int row = 32 * w + 16 * (r >> 1) + 8 * (r & 1) + g;
                uint32_t off = (uint32_t)row * ROWB + (uint32_t)cq * 16u;
                *(uint4*)(KH + off) = make_uint4(oh[r][0], oh[r][1], oh[r][2], oh[r][3]);
                *(uint4*)(KL + off) = make_uint4(ol[r][0], ol[r][1], ol[r][2], ol[r][3]);
            }
            __syncwarp();                                   // order all lanes' STS
            if (l == 0) {
                asm volatile("st.release.cta.shared.b32 [%0], %1;"
                             :: "r"(smem_u32(&s_flag[w])), "r"(1) : "memory");
            }
        }

        // q: outputs straight into A-fragment registers
        {
            #pragma unroll
            for (int nt = 0; nt < 4; nt++) {
                uint32_t woff = (uint32_t)(8 * nt + g) * ROWB + (uint32_t)cq * 16u;
                uint4 wh = *(const uint4*)(dsm + OFF_WQH + woff);
                uint4 wl = *(const uint4*)(dsm + OFF_WQL + woff);
                float2 bb = *(const float2*)(s_bq + 8 * nt + 2 * cq);
                #pragma unroll
                for (int mt = 0; mt < 2; mt++) {
                    float a4[4] = {bb.x, bb.y, bb.x, bb.y};
                    mma16816(a4, ah[mt][0], wh.x, wh.y);
                    mma16816(a4, ah[mt][1], wh.z, wh.w);
                    mma16816(a4, ah[mt][0], wl.x, wl.y);
                    mma16816(a4, ah[mt][1], wl.z, wl.w);
                    mma16816(a4, al[mt][0], wh.x, wh.y);
                    mma16816(a4, al[mt][1], wh.z, wh.w);
                    const int k2 = nt >> 1, hx = 2 * (nt & 1);
                    psplit(fmaxf(a4[0], 0.0f), fmaxf(a4[1], 0.0f),
                           aqh[mt][k2][hx + 0], aql[mt][k2][hx + 0]);   // row g
                    psplit(fmaxf(a4[2], 0.0f), fmaxf(a4[3], 0.0f),
                           aqh[mt][k2][hx + 1], aql[mt][k2][hx + 1]);   // row g+8
                }
            }
        }
    }

    // ---- 4. attention: rotated producer order, acquire-poll per producer ----
    float stD[4], stN[4];
    #pragma unroll
    for (int r = 0; r < 4; r++) { stD[r] = 0.0f; stN[r] = 0.0f; }

    const char* KHg = KH + (uint32_t)g * ROWB + (uint32_t)cq * 16u;
    const char* KLg = KL + (uint32_t)g * ROWB + (uint32_t)cq * 16u;

    #pragma unroll 1
    for (int j = 0; j < 8; j++) {
        const int p = (w + j) & 7;
        if (j) {
            uint32_t fa = smem_u32(&s_flag[p]);
            uint32_t v;
            do {
                asm volatile("ld.acquire.cta.shared.b32 %0, [%1];"
                             : "=r"(v) : "r"(fa) : "memory");
            } while (v == 0);
        }
        #pragma unroll
        for (int q2 = 0; q2 < 2; q2++) {
            const int ch = 2 * p + q2;
            uint4 bh[2], blo[2];
            #pragma unroll
            for (int nt = 0; nt < 2; nt++) {
                bh[nt]  = *(const uint4*)(KHg + ((uint32_t)ch * 16u + 8u * nt) * ROWB);
                blo[nt] = *(const uint4*)(KLg + ((uint32_t)ch * 16u + 8u * nt) * ROWB);
            }
            float2 v0 = *(const float2*)&s_v[16 * ch + 2 * cq];
            float2 v1 = *(const float2*)&s_v[16 * ch + 8 + 2 * cq];

            float acc[2][2][4];
            #pragma unroll
            for (int mt = 0; mt < 2; mt++)
                #pragma unroll
                for (int nt = 0; nt < 2; nt++) {
                    float* a = acc[mt][nt];
                    a[0] = a[1] = a[2] = a[3] = -32.0f;   // constant softmax shift
                    mma16816(a, aqh[mt][0], bh[nt].x,  bh[nt].y);
                    mma16816(a, aqh[mt][1], bh[nt].z,  bh[nt].w);
                    mma16816(a, aqh[mt][0], blo[nt].x, blo[nt].y);
                    mma16816(a, aqh[mt][1], blo[nt].z, blo[nt].w);
                    mma16816(a, aql[mt][0], bh[nt].x,  bh[nt].y);
                    mma16816(a, aql[mt][1], bh[nt].z,  bh[nt].w);
                }

            #pragma unroll
            for (int mt = 0; mt < 2; mt++)
                #pragma unroll
                for (int i = 0; i < 2; i++) {
                    int r = mt * 2 + i;
                    float e0 = ex2f(acc[mt][0][2 * i + 0]);
                    float e1 = ex2f(acc[mt][0][2 * i + 1]);
                    float e2 = ex2f(acc[mt][1][2 * i + 0]);
                    float e3 = ex2f(acc[mt][1][2 * i + 1]);
                    stD[r] += (e0 + e1) + (e2 + e3);
                    stN[r] += (e0 * v0.x + e1 * v0.y) + (e2 * v1.x + e3 * v1.y);
                }
        }
    }

    // ---- quad merge (pure adds) + write ----
    #pragma unroll
    for (int r = 0; r < 4; r++) {
        #pragma unroll
        for (int off = 1; off <= 2; off <<= 1) {
            stD[r] += __shfl_xor_sync(0xffffffffu, stD[r], off);
            stN[r] += __shfl_xor_sync(0xffffffffu, stN[r], off);
        }
    }
    if (cq == 0) {
        #pragma unroll
        for (int r = 0; r < 4; r++) {
            int row = 32 * w + (r >> 1) * 16 + (r & 1) * 8 + g;
            out[((size_t)(b * 256 + row)) * TB + t] = s_v[row] + stN[r] / stD[r];
        }
    }
}

extern "C" void kernel_launch(void* const* d_in, const int* in_sizes, int n_in,
                              void* d_out, int out_size) {
    const float* x    = (const float*)d_in[0];
    const float* kw   = (const float*)d_in[1];
    const float* kb   = (const float*)d_in[2];
    const float* kg   = (const float*)d_in[3];
    const float* kbe  = (const float*)d_in[4];
    const float* qw   = (const float*)d_in[5];
    const float* qb   = (const float*)d_in[6];
    const float* qg   = (const float*)d_in[7];
    const float* qbe  = (const float*)d_in[8];
    float* o = (float*)d_out;

    cudaFuncSetAttribute(csa_mma_kernel, cudaFuncAttributeMaxDynamicSharedMemorySize, DSMEM_BYTES);
    dim3 grid(TB, BB);
    csa_mma_kernel<<<grid, 256, DSMEM_BYTES>>>(x, kw, kb, kg, kbe, qw, qb, qg, qbe, o);
}

// round 17
// speedup vs baseline: 1.5369x; 1.3689x over previous
#include <cuda_runtime.h>
#include <cuda_bf16.h>
#include <cuda_fp16.h>
#include <cstdint>

#define TB 1024
#define BB 4
#define ROWB 64u     // bytes per granule row: 32 halfwords
#define XROW 33      // f32 staging row stride (floats), conflict-free

// dynamic smem layout (bytes); staging f32 buf = [0, 33792) overlays FH/FL
#define OFF_FH   0u
#define OFF_FL   16384u
#define OFF_KH   33792u      // fp16 K granules (no KL needed)
#define OFF_WQH  50176u
#define OFF_WQL  52224u
#define OFF_WKH  54272u
#define OFF_WKL  56320u
#define DSMEM_BYTES 58368

// Granule layout: row r = 4 x uint4; slot s comp j = pair (s+4j) = cols {2(s+4j), 2(s+4j)+1}.

// ---------------- helpers ----------------
static __device__ __forceinline__ float ex2f(float v) {
    float y; asm("ex2.approx.ftz.f32 %0, %1;" : "=f"(y) : "f"(v)); return y;
}
// bf16 hi/lo split of a pair (projection inputs/weights)
static __device__ __forceinline__ void psplit(float e, float o, uint32_t& hi, uint32_t& lo) {
    __nv_bfloat16 he = __float2bfloat16(e), ho = __float2bfloat16(o);
    __nv_bfloat162 hp(he, ho);
    hi = *reinterpret_cast<uint32_t*>(&hp);
    __nv_bfloat162 lp(__float2bfloat16(e - __bfloat162float(he)),
                      __float2bfloat16(o - __bfloat162float(ho)));
    lo = *reinterpret_cast<uint32_t*>(&lp);
}
// fp16 pack of a pair (attention operands)
static __device__ __forceinline__ uint32_t hpack(float e, float o) {
    __half2 h = __floats2half2_rn(e, o);
    return *reinterpret_cast<uint32_t*>(&h);
}
// m16n8k16 row.col f32.bf16.bf16.f32, D += A*B
static __device__ __forceinline__ void mma_bf16(float* d, const uint32_t* a,
                                                uint32_t b0, uint32_t b1) {
    asm("mma.sync.aligned.m16n8k16.row.col.f32.bf16.bf16.f32 "
        "{%0,%1,%2,%3}, {%4,%5,%6,%7}, {%8,%9}, {%0,%1,%2,%3};"
        : "+f"(d[0]), "+f"(d[1]), "+f"(d[2]), "+f"(d[3])
        : "r"(a[0]), "r"(a[1]), "r"(a[2]), "r"(a[3]), "r"(b0), "r"(b1));
}
// m16n8k16 row.col f32.f16.f16.f32, D += A*B
static __device__ __forceinline__ void mma_f16(float* d, const uint32_t* a,
                                               uint32_t b0, uint32_t b1) {
    asm("mma.sync.aligned.m16n8k16.row.col.f32.f16.f16.f32 "
        "{%0,%1,%2,%3}, {%4,%5,%6,%7}, {%8,%9}, {%0,%1,%2,%3};"
        : "+f"(d[0]), "+f"(d[1]), "+f"(d[2]), "+f"(d[3])
        : "r"(a[0]), "r"(a[1]), "r"(a[2]), "r"(a[3]), "r"(b0), "r"(b1));
}

// ---------------- kernel ----------------
// One CTA per (b,t), 256 threads, 2 CTAs/SM. All GEMMs on HMMA.
// Projection: bf16 hi/lo 3-term (q,k accurate to ~4e-6).
// Attention: SINGLE-term fp16 q.k (11-bit mantissa; dot rel err ~7e-4 ->
//            output rel err ~1e-4, 10x under threshold). 2 MMAs/chunk vs 6.
// Softmax: max-free log2 domain, constant shift -32 (logits >= 0).
__global__ void __launch_bounds__(256, 2)
csa_mma_kernel(const float* __restrict__ x,
               const float* __restrict__ kw,  const float* __restrict__ kbias,
               const float* __restrict__ kg,  const float* __restrict__ kbeta,
               const float* __restrict__ qw,  const float* __restrict__ qbias,
               const float* __restrict__ qg,  const float* __restrict__ qbeta,
               float* __restrict__ out)
{
    extern __shared__ char dsm[];
    __shared__ __align__(8) float s_v[256];
    __shared__ float s_bq[32], s_bk[32];

    float* s_x = (float*)dsm;                 // staging (overlaid by FH/FL later)
    char* FH = dsm + OFF_FH;  char* FL = dsm + OFF_FL;
    char* KH = dsm + OFF_KH;

    const int t   = blockIdx.x;
    const int b   = blockIdx.y;
    const int tid = threadIdx.x;
    const int w   = tid >> 5;
    const int l   = tid & 31;
    const int g   = l >> 2;    // fragment row group
    const int cq  = l & 3;     // quad col id (granule slot)

    const float inv    = rsqrtf(1.0f + 1e-5f);
    const float qscale = 0.17677669529663687f * 1.4426950408889634f; // (1/sqrt32)*log2(e)

    // ---- 1a. stage windows coalesced: lane = time offset ----
    {
        const float* xb = x + ((size_t)b * 256) * TB;
        #pragma unroll
        for (int i = tid; i < 256 * 32; i += 256) {
            int c = i >> 5, d = i & 31;
            int tau = t - 31 + d;
            s_x[c * XROW + d] = (tau >= 0) ? xb[(size_t)c * TB + tau] : 0.0f;
        }
    }

    // ---- 1b. weight granules (folded BN; qscale folded into q) + biases ----
    {
        const int m    = tid >> 7;          // 0 = q, 1 = k
        const int slot = tid & 127;
        const int s    = slot >> 2;
        const int i    = slot & 3;
        const float* wsrc = m ? kw : qw;
        const float* gsrc = m ? kg : qg;
        float gs = gsrc[s] * inv * (m ? 1.0f : qscale);
        uint32_t gh[4], gl[4];
        #pragma unroll
        for (int j = 0; j < 4; j++) {
            int d0 = 2 * (i + 4 * j);
            float2 wv = *(const float2*)(wsrc + s * 32 + d0);
            psplit(wv.x * gs, wv.y * gs, gh[j], gl[j]);
        }
        char* WH = dsm + (m ? OFF_WKH : OFF_WQH);
        char* WL = dsm + (m ? OFF_WKL : OFF_WQL);
        *(uint4*)(WH + s * 64 + i * 16) = make_uint4(gh[0], gh[1], gh[2], gh[3]);
        *(uint4*)(WL + s * 64 + i * 16) = make_uint4(gl[0], gl[1], gl[2], gl[3]);
        if (tid < 32)
            s_bq[tid] = (qbias[tid] * qg[tid] * inv + qbeta[tid]) * qscale;
        else if (tid < 64) {
            int ss = tid - 32;
            s_bk[ss] = kbias[ss] * kg[ss] * inv + kbeta[ss];
        }
    }
    __syncthreads();

    // ---- 2. split own framed row -> granule regs; overlay-store after sync ----
    uint32_t fh[4][4], fl[4][4];
    {
        const float* xr = s_x + tid * XROW;
        float f[32];
        #pragma unroll
        for (int d = 0; d < 32; d++) f[d] = xr[d];
        s_v[tid] = f[31];
        #pragma unroll
        for (int i = 0; i < 4; i++)
            #pragma unroll
            for (int j = 0; j < 4; j++) {
                int d0 = 2 * (i + 4 * j);
                psplit(f[d0], f[d0 + 1], fh[i][j], fl[i][j]);
            }
    }
    __syncthreads();
    {
        uint4* dh = (uint4*)(FH + tid * ROWB);
        uint4* dl = (uint4*)(FL + tid * ROWB);
        #pragma unroll
        for (int i = 0; i < 4; i++) {
            dh[i] = make_uint4(fh[i][0], fh[i][1], fh[i][2], fh[i][3]);
            dl[i] = make_uint4(fl[i][0], fl[i][1], fl[i][2], fl[i][3]);
        }
    }
    __syncthreads();

    // ---- 3. projection MMA (bf16 3-term) ----
    uint32_t aq[2][2][4];                  // attention A-frags, fp16 (q outputs)
    {
        uint32_t ah[2][2][4], al[2][2][4];
        #pragma unroll
        for (int mt = 0; mt < 2; mt++) {
            uint32_t r0 = (uint32_t)(32 * w + 16 * mt + g) * ROWB + (uint32_t)cq * 16u;
            uint4 h0 = *(const uint4*)(FH + r0);
            uint4 h1 = *(const uint4*)(FH + r0 + 8 * ROWB);
            uint4 l0 = *(const uint4*)(FL + r0);
            uint4 l1 = *(const uint4*)(FL + r0 + 8 * ROWB);
            ah[mt][0][0] = h0.x; ah[mt][0][1] = h1.x; ah[mt][0][2] = h0.y; ah[mt][0][3] = h1.y;
            ah[mt][1][0] = h0.z; ah[mt][1][1] = h1.z; ah[mt][1][2] = h0.w; ah[mt][1][3] = h1.w;
            al[mt][0][0] = l0.x; al[mt][0][1] = l1.x; al[mt][0][2] = l0.y; al[mt][0][3] = l1.y;
            al[mt][1][0] = l0.z; al[mt][1][1] = l1.z; al[mt][1][2] = l0.w; al[mt][1][3] = l1.w;
        }

        // q: outputs straight into fp16 A-fragment registers
        {
            #pragma unroll
            for (int nt = 0; nt < 4; nt++) {
                uint32_t woff = (uint32_t)(8 * nt + g) * ROWB + (uint32_t)cq * 16u;
                uint4 wh = *(const uint4*)(dsm + OFF_WQH + woff);
                uint4 wl = *(const uint4*)(dsm + OFF_WQL + woff);
                float2 bb = *(const float2*)(s_bq + 8 * nt + 2 * cq);
                #pragma unroll
                for (int mt = 0; mt < 2; mt++) {
                    float a4[4] = {bb.x, bb.y, bb.x, bb.y};
                    mma_bf16(a4, ah[mt][0], wh.x, wh.y);
                    mma_bf16(a4, ah[mt][1], wh.z, wh.w);
                    mma_bf16(a4, ah[mt][0], wl.x, wl.y);
                    mma_bf16(a4, ah[mt][1], wl.z, wl.w);
                    mma_bf16(a4, al[mt][0], wh.x, wh.y);
                    mma_bf16(a4, al[mt][1], wh.z, wh.w);
                    const int k2 = nt >> 1, hx = 2 * (nt & 1);
                    aq[mt][k2][hx + 0] = hpack(fmaxf(a4[0], 0.0f), fmaxf(a4[1], 0.0f)); // row g
                    aq[mt][k2][hx + 1] = hpack(fmaxf(a4[2], 0.0f), fmaxf(a4[3], 0.0f)); // row g+8
                }
            }
        }

        // k: fp16 outputs -> smem granules (KH only)
        {
            uint32_t oh[4][4];
            #pragma unroll
            for (int nt = 0; nt < 4; nt++) {
                uint32_t woff = (uint32_t)(8 * nt + g) * ROWB + (uint32_t)cq * 16u;
                uint4 wh = *(const uint4*)(dsm + OFF_WKH + woff);
                uint4 wl = *(const uint4*)(dsm + OFF_WKL + woff);
                float2 bb = *(const float2*)(s_bk + 8 * nt + 2 * cq);
                #pragma unroll
                for (int mt = 0; mt < 2; mt++) {
                    float a4[4] = {bb.x, bb.y, bb.x, bb.y};
                    mma_bf16(a4, ah[mt][0], wh.x, wh.y);
                    mma_bf16(a4, ah[mt][1], wh.z, wh.w);
                    mma_bf16(a4, ah[mt][0], wl.x, wl.y);
                    mma_bf16(a4, ah[mt][1], wl.z, wl.w);
                    mma_bf16(a4, al[mt][0], wh.x, wh.y);
                    mma_bf16(a4, al[mt][1], wh.z, wh.w);
                    #pragma unroll
                    for (int i = 0; i < 2; i++)
                        oh[mt * 2 + i][nt] = hpack(fmaxf(a4[2 * i + 0], 0.0f),
                                                   fmaxf(a4[2 * i + 1], 0.0f));
                }
            }
            #pragma unroll
            for (int r = 0; r < 4; r++) {
                int row = 32 * w + 16 * (r >> 1) + 8 * (r & 1) + g;
                uint32_t off = (uint32_t)row * ROWB + (uint32_t)cq * 16u;
                *(uint4*)(KH + off) = make_uint4(oh[r][0], oh[r][1], oh[r][2], oh[r][3]);
            }
        }
    }
    __syncthreads();

    // ---- 4. attention: single fp16 term; max-free, acc init -32 (exact shift) ----
    float stD[4], stN[4];
    #pragma unroll
    for (int r = 0; r < 4; r++) { stD[r] = 0.0f; stN[r] = 0.0f; }

    const char* KHg = KH + (uint32_t)g * ROWB + (uint32_t)cq * 16u;

    #pragma unroll 4
    for (int ch = 0; ch < 16; ch++) {
        uint4 bh[2];
        #pragma unroll
        for (int nt = 0; nt < 2; nt++)
            bh[nt] = *(const uint4*)(KHg + ((uint32_t)ch * 16u + 8u * nt) * ROWB);
        float2 v0 = *(const float2*)&s_v[16 * ch + 2 * cq];
        float2 v1 = *(const float2*)&s_v[16 * ch + 8 + 2 * cq];

        float acc[2][2][4];
        #pragma unroll
        for (int mt = 0; mt < 2; mt++)
            #pragma unroll
            for (int nt = 0; nt < 2; nt++) {
                float* a = acc[mt][nt];
                a[0] = a[1] = a[2] = a[3] = -32.0f;   // constant softmax shift
                mma_f16(a, aq[mt][0], bh[nt].x, bh[nt].y);
                mma_f16(a, aq[mt][1], bh[nt].z, bh[nt].w);
            }

        #pragma unroll
        for (int mt = 0; mt < 2; mt++)
            #pragma unroll
            for (int i = 0; i < 2; i++) {
                int r = mt * 2 + i;
                float e0 = ex2f(acc[mt][0][2 * i + 0]);
                float e1 = ex2f(acc[mt][0][2 * i + 1]);
                float e2 = ex2f(acc[mt][1][2 * i + 0]);
                float e3 = ex2f(acc[mt][1][2 * i + 1]);
                stD[r] += (e0 + e1) + (e2 + e3);
                stN[r] += (e0 * v0.x + e1 * v0.y) + (e2 * v1.x + e3 * v1.y);
            }
    }

    // ---- quad merge (pure adds) + write ----
    #pragma unroll
    for (int r = 0; r < 4; r++) {
        #pragma unroll
        for (int off = 1; off <= 2; off <<= 1) {
            stD[r] += __shfl_xor_sync(0xffffffffu, stD[r], off);
            stN[r] += __shfl_xor_sync(0xffffffffu, stN[r], off);
        }
    }
    if (cq == 0) {
        #pragma unroll
        for (int r = 0; r < 4; r++) {
            int row = 32 * w + (r >> 1) * 16 + (r & 1) * 8 + g;
            out[((size_t)(b * 256 + row)) * TB + t] = s_v[row] + stN[r] / stD[r];
        }
    }
}

extern "C" void kernel_launch(void* const* d_in, const int* in_sizes, int n_in,
                              void* d_out, int out_size) {
    const float* x    = (const float*)d_in[0];
    const float* kw   = (const float*)d_in[1];
    const float* kb   = (const float*)d_in[2];
    const float* kg   = (const float*)d_in[3];
    const float* kbe  = (const float*)d_in[4];
    const float* qw   = (const float*)d_in[5];
    const float* qb   = (const float*)d_in[6];
    const float* qg   = (const float*)d_in[7];
    const float* qbe  = (const float*)d_in[8];
    float* o = (float*)d_out;

    cudaFuncSetAttribute(csa_mma_kernel, cudaFuncAttributeMaxDynamicSharedMemorySize, DSMEM_BYTES);
    dim3 grid(TB, BB);
    csa_mma_kernel<<<grid, 256, DSMEM_BYTES>>>(x, kw, kb, kg, kbe, qw, qb, qg, qbe, o);
}